// round 10
// baseline (speedup 1.0000x reference)
#include <cuda_runtime.h>
#include <cuda_bf16.h>
#include <math.h>

#define NN   50000
#define FIN  128
#define HID  64
#define H1   4
#define NGR  512
#define EE   800000
#define ET   (EE + NN)        // 850000 edges incl. self loops
#define C1   (H1 * HID)       // 256 = layer-1 width

// ---------------- scratch (device globals; no allocation allowed) -----------
__device__ __align__(16) float g_h1[(size_t)NN * C1];     // x @ W1
__device__ __align__(16) float g_out1[(size_t)NN * C1];   // GAT1 aggregate
__device__ __align__(16) float g_h2[(size_t)NN * HID];    // relu(out1+b1) @ W2
__device__ __align__(16) float g_out2[(size_t)NN * HID];  // GAT2 aggregate
__device__ __align__(16) float g_asrc1[(size_t)NN * H1];
__device__ __align__(16) float g_adst1[(size_t)NN * H1];
__device__ float g_asrc2[NN];
__device__ float g_adst2[NN];
__device__ float g_pool[(size_t)NGR * HID];
__device__ float g_cnt[NGR];
// CSR by destination node
__device__ int g_deg[NN];
__device__ int g_wr[NN];          // running write cursor (seeded with rowptr)
__device__ int g_rowptr[NN + 1];
__device__ int g_csr_src[ET];
__device__ int g_csr_dst[ET];
// per-edge softmax numerators, CSR order
__device__ __align__(16) float g_p1[(size_t)ET * H1];
__device__ float g_p2[ET];

__device__ __forceinline__ float lrelu(float v) { return v > 0.f ? v : 0.2f * v; }

__device__ __forceinline__ int clampn(int v, int hi) {
    return v < 0 ? 0 : (v >= hi ? hi - 1 : v);
}

// ---------------- CSR build -------------------------------------------------

__global__ void zero_kernel() {
    int i = blockIdx.x * 256 + threadIdx.x;
    if (i < NN) g_deg[i] = 0;
    if (i < NGR * HID) g_pool[i] = 0.f;
    if (i < NGR) g_cnt[i] = 0.f;
}

__global__ void deg_kernel(const int* __restrict__ ei) {
    int e = blockIdx.x * 256 + threadIdx.x;
    if (e >= ET) return;
    int d = (e < EE) ? clampn(ei[EE + e], NN) : e - EE;
    atomicAdd(&g_deg[d], 1);
}

// single-block exclusive scan of deg -> rowptr; also seeds g_wr with rowptr
__global__ void scan_kernel() {
    __shared__ int wsum[32];
    __shared__ int carry_s;
    int tid = threadIdx.x, lane = tid & 31, w = tid >> 5;
    if (tid == 0) { carry_s = 0; g_rowptr[0] = 0; g_wr[0] = 0; }
    __syncthreads();
    for (int base = 0; base < NN; base += 1024) {
        int i = base + tid;
        int x = (i < NN) ? g_deg[i] : 0;
#pragma unroll
        for (int off = 1; off < 32; off <<= 1) {
            int t = __shfl_up_sync(0xffffffffu, x, off);
            if (lane >= off) x += t;
        }
        if (lane == 31) wsum[w] = x;
        __syncthreads();
        if (w == 0) {
            int s = wsum[lane];
#pragma unroll
            for (int off = 1; off < 32; off <<= 1) {
                int t = __shfl_up_sync(0xffffffffu, s, off);
                if (lane >= off) s += t;
            }
            wsum[lane] = s;
        }
        __syncthreads();
        int incl = x + (w > 0 ? wsum[w - 1] : 0) + carry_s;
        if (i < NN) {
            g_rowptr[i + 1] = incl;
            if (i + 1 < NN) g_wr[i + 1] = incl;   // exclusive prefix for node i+1
        }
        __syncthreads();
        if (tid == 1023) carry_s = incl;
        __syncthreads();
    }
}

__global__ void scatter_kernel(const int* __restrict__ ei) {
    int e = blockIdx.x * 256 + threadIdx.x;
    if (e >= ET) return;
    int s, d;
    if (e < EE) {
        s = clampn(ei[e], NN);
        d = clampn(ei[EE + e], NN);
    } else {
        s = d = e - EE;
    }
    int pos = atomicAdd(&g_wr[d], 1);
    g_csr_src[pos] = s;
    g_csr_dst[pos] = d;
}

// ---------------- dense kernels ---------------------------------------------

// C[M=NN, 256] = X[M,128] @ W1[128,256]
__global__ void gemm1_kernel(const float* __restrict__ X, const float* __restrict__ W) {
    __shared__ float As[16][128];
    __shared__ float Bs[16][128];
    const int bm = blockIdx.x * 128;
    const int bn = blockIdx.y * 128;
    const int tid = threadIdx.x;           // 256
    const int tx = tid & 15, ty = tid >> 4;
    float acc[8][8];
#pragma unroll
    for (int i = 0; i < 8; i++)
#pragma unroll
        for (int j = 0; j < 8; j++) acc[i][j] = 0.f;

    for (int k0 = 0; k0 < FIN; k0 += 16) {
#pragma unroll
        for (int i = 0; i < 2; i++) {              // A tile 128x16 (transposed store)
            int idx = tid + i * 256;               // 512 float4
            int row = idx >> 2;
            int kc  = (idx & 3) * 4;
            float4 v = make_float4(0.f, 0.f, 0.f, 0.f);
            int gr = bm + row;
            if (gr < NN) v = *reinterpret_cast<const float4*>(&X[(size_t)gr * FIN + k0 + kc]);
            As[kc + 0][row] = v.x; As[kc + 1][row] = v.y;
            As[kc + 2][row] = v.z; As[kc + 3][row] = v.w;
        }
#pragma unroll
        for (int i = 0; i < 2; i++) {              // B tile 16x128
            int idx = tid + i * 256;
            int kr = idx >> 5;
            int nc = (idx & 31) * 4;
            *reinterpret_cast<float4*>(&Bs[kr][nc]) =
                *reinterpret_cast<const float4*>(&W[(size_t)(k0 + kr) * C1 + bn + nc]);
        }
        __syncthreads();
#pragma unroll
        for (int kk = 0; kk < 16; kk++) {
            float a[8], b[8];
#pragma unroll
            for (int i = 0; i < 8; i++) a[i] = As[kk][ty * 8 + i];
#pragma unroll
            for (int j = 0; j < 8; j++) b[j] = Bs[kk][tx * 8 + j];
#pragma unroll
            for (int i = 0; i < 8; i++)
#pragma unroll
                for (int j = 0; j < 8; j++) acc[i][j] += a[i] * b[j];
        }
        __syncthreads();
    }
#pragma unroll
    for (int i = 0; i < 8; i++) {
        int gr = bm + ty * 8 + i;
        if (gr < NN) {
            float4* dst = reinterpret_cast<float4*>(&g_h1[(size_t)gr * C1 + bn + tx * 8]);
            dst[0] = make_float4(acc[i][0], acc[i][1], acc[i][2], acc[i][3]);
            dst[1] = make_float4(acc[i][4], acc[i][5], acc[i][6], acc[i][7]);
        }
    }
}

// asrc1/adst1[n,h] = dot(h1[n, h*64 : (h+1)*64], a_{src,dst}1[h])
__global__ void att1_kernel(const float* __restrict__ a_src, const float* __restrict__ a_dst) {
    __shared__ float sa[C1], sd[C1];
    int tid = threadIdx.x;
    sa[tid] = a_src[tid];
    sd[tid] = a_dst[tid];
    __syncthreads();
    int warp = tid >> 5, lane = tid & 31;
    int n = blockIdx.x * 8 + warp;
    if (n >= NN) return;
    const float* hr = &g_h1[(size_t)n * C1];
#pragma unroll
    for (int h = 0; h < H1; h++) {
        float x0 = hr[h * 64 + lane], x1 = hr[h * 64 + 32 + lane];
        float va = x0 * sa[h * 64 + lane] + x1 * sa[h * 64 + 32 + lane];
        float vd = x0 * sd[h * 64 + lane] + x1 * sd[h * 64 + 32 + lane];
#pragma unroll
        for (int off = 16; off > 0; off >>= 1) {
            va += __shfl_down_sync(0xffffffffu, va, off);
            vd += __shfl_down_sync(0xffffffffu, vd, off);
        }
        if (lane == 0) { g_asrc1[n * H1 + h] = va; g_adst1[n * H1 + h] = vd; }
    }
}

// per-CSR-slot softmax numerators, layer 1 (coalesced write of float4)
__global__ void edgeP1_kernel() {
    int j = blockIdx.x * 256 + threadIdx.x;
    if (j >= ET) return;
    int s = g_csr_src[j], d = g_csr_dst[j];
    float4 as = *reinterpret_cast<const float4*>(&g_asrc1[(size_t)s * H1]);
    float4 ad = *reinterpret_cast<const float4*>(&g_adst1[(size_t)d * H1]);
    float4 p;
    p.x = __expf(lrelu(as.x + ad.x));
    p.y = __expf(lrelu(as.y + ad.y));
    p.z = __expf(lrelu(as.z + ad.z));
    p.w = __expf(lrelu(as.w + ad.w));
    *reinterpret_cast<float4*>(&g_p1[(size_t)j * H1]) = p;
}

// fused softmax-normalize + aggregate, layer 1: one warp per dst node.
// pass 1: lane-parallel sum of p1 (float4/lane, strided), butterfly reduce.
// pass 2: lane -> head = lane>>3, part = lane&7; alpha from p1 (broadcast load).
__global__ void gather1_kernel() {
    int warp = blockIdx.x * 8 + (threadIdx.x >> 5);
    if (warp >= NN) return;
    const int d = warp;
    const int lane = threadIdx.x & 31;
    const int head = lane >> 3, part = lane & 7;

    const int r0 = g_rowptr[d], r1 = g_rowptr[d + 1];

    float4 s4 = make_float4(0.f, 0.f, 0.f, 0.f);
    for (int j = r0 + lane; j < r1; j += 32) {
        float4 p = *reinterpret_cast<const float4*>(&g_p1[(size_t)j * H1]);
        s4.x += p.x; s4.y += p.y; s4.z += p.z; s4.w += p.w;
    }
#pragma unroll
    for (int off = 16; off > 0; off >>= 1) {
        s4.x += __shfl_xor_sync(0xffffffffu, s4.x, off);
        s4.y += __shfl_xor_sync(0xffffffffu, s4.y, off);
        s4.z += __shfl_xor_sync(0xffffffffu, s4.z, off);
        s4.w += __shfl_xor_sync(0xffffffffu, s4.w, off);
    }
    float sh = head == 0 ? s4.x : head == 1 ? s4.y : head == 2 ? s4.z : s4.w;
    const float rs = 1.f / (sh + 1e-16f);

    float a0 = 0.f, a1 = 0.f, a2 = 0.f, a3 = 0.f, a4 = 0.f, a5 = 0.f, a6 = 0.f, a7 = 0.f;
    for (int j = r0; j < r1; j++) {
        int s = g_csr_src[j];
        float4 pv = *reinterpret_cast<const float4*>(&g_p1[(size_t)j * H1]);
        float al = (head == 0 ? pv.x : head == 1 ? pv.y : head == 2 ? pv.z : pv.w) * rs;
        const float4* hp =
            reinterpret_cast<const float4*>(&g_h1[(size_t)s * C1 + head * 64 + part * 8]);
        float4 v0 = hp[0], v1 = hp[1];
        a0 += al * v0.x; a1 += al * v0.y; a2 += al * v0.z; a3 += al * v0.w;
        a4 += al * v1.x; a5 += al * v1.y; a6 += al * v1.z; a7 += al * v1.w;
    }
    float4* o = reinterpret_cast<float4*>(&g_out1[(size_t)d * C1 + head * 64 + part * 8]);
    o[0] = make_float4(a0, a1, a2, a3);
    o[1] = make_float4(a4, a5, a6, a7);
}

// h2[M=NN, 64] = relu(out1 + b1)[M,256] @ W2[256,64]   (bias+relu fused into A load)
__global__ void gemm2_kernel(const float* __restrict__ W2, const float* __restrict__ b1) {
    __shared__ float As[16][128];
    __shared__ float Bs[16][64];
    const int bm = blockIdx.x * 128;
    const int tid = threadIdx.x;           // 256
    const int tx = tid & 15, ty = tid >> 4;
    float acc[8][4];
#pragma unroll
    for (int i = 0; i < 8; i++)
#pragma unroll
        for (int j = 0; j < 4; j++) acc[i][j] = 0.f;

    const float* A = g_out1;
    for (int k0 = 0; k0 < C1; k0 += 16) {
#pragma unroll
        for (int i = 0; i < 2; i++) {
            int idx = tid + i * 256;
            int row = idx >> 2;
            int kc  = (idx & 3) * 4;
            float4 v = make_float4(0.f, 0.f, 0.f, 0.f);
            int gr = bm + row;
            if (gr < NN) v = *reinterpret_cast<const float4*>(&A[(size_t)gr * C1 + k0 + kc]);
            As[kc + 0][row] = fmaxf(v.x + __ldg(&b1[k0 + kc + 0]), 0.f);
            As[kc + 1][row] = fmaxf(v.y + __ldg(&b1[k0 + kc + 1]), 0.f);
            As[kc + 2][row] = fmaxf(v.z + __ldg(&b1[k0 + kc + 2]), 0.f);
            As[kc + 3][row] = fmaxf(v.w + __ldg(&b1[k0 + kc + 3]), 0.f);
        }
        {   // B tile 16x64 = 256 float4, one per thread
            int kr = tid >> 4;
            int nc = (tid & 15) * 4;
            *reinterpret_cast<float4*>(&Bs[kr][nc]) =
                *reinterpret_cast<const float4*>(&W2[(size_t)(k0 + kr) * HID + nc]);
        }
        __syncthreads();
#pragma unroll
        for (int kk = 0; kk < 16; kk++) {
            float a[8], b[4];
#pragma unroll
            for (int i = 0; i < 8; i++) a[i] = As[kk][ty * 8 + i];
#pragma unroll
            for (int j = 0; j < 4; j++) b[j] = Bs[kk][tx * 4 + j];
#pragma unroll
            for (int i = 0; i < 8; i++)
#pragma unroll
                for (int j = 0; j < 4; j++) acc[i][j] += a[i] * b[j];
        }
        __syncthreads();
    }
#pragma unroll
    for (int i = 0; i < 8; i++) {
        int gr = bm + ty * 8 + i;
        if (gr < NN)
            *reinterpret_cast<float4*>(&g_h2[(size_t)gr * HID + tx * 4]) =
                make_float4(acc[i][0], acc[i][1], acc[i][2], acc[i][3]);
    }
}

__global__ void att2_kernel(const float* __restrict__ a_src, const float* __restrict__ a_dst) {
    __shared__ float sa[HID], sd[HID];
    int tid = threadIdx.x;
    if (tid < HID) { sa[tid] = a_src[tid]; sd[tid] = a_dst[tid]; }
    __syncthreads();
    int warp = tid >> 5, lane = tid & 31;
    int n = blockIdx.x * 8 + warp;
    if (n >= NN) return;
    float x0 = g_h2[(size_t)n * HID + lane], x1 = g_h2[(size_t)n * HID + 32 + lane];
    float va = x0 * sa[lane] + x1 * sa[32 + lane];
    float vd = x0 * sd[lane] + x1 * sd[32 + lane];
#pragma unroll
    for (int off = 16; off > 0; off >>= 1) {
        va += __shfl_down_sync(0xffffffffu, va, off);
        vd += __shfl_down_sync(0xffffffffu, vd, off);
    }
    if (lane == 0) { g_asrc2[n] = va; g_adst2[n] = vd; }
}

__global__ void edgeP2_kernel() {
    int j = blockIdx.x * 256 + threadIdx.x;
    if (j >= ET) return;
    int s = g_csr_src[j], d = g_csr_dst[j];
    g_p2[j] = __expf(lrelu(g_asrc2[s] + g_adst2[d]));
}

// fused normalize + aggregate, layer 2: one warp per dst, lane -> 2 floats of 64
__global__ void gather2_kernel() {
    int warp = blockIdx.x * 8 + (threadIdx.x >> 5);
    if (warp >= NN) return;
    const int d = warp;
    const int lane = threadIdx.x & 31;

    const int r0 = g_rowptr[d], r1 = g_rowptr[d + 1];

    float sum = 0.f;
    for (int j = r0 + lane; j < r1; j += 32) sum += g_p2[j];
#pragma unroll
    for (int off = 16; off > 0; off >>= 1)
        sum += __shfl_xor_sync(0xffffffffu, sum, off);
    const float rs = 1.f / (sum + 1e-16f);

    float a0 = 0.f, a1 = 0.f;
    for (int j = r0; j < r1; j++) {
        int s = g_csr_src[j];
        float al = g_p2[j] * rs;
        float2 v = *reinterpret_cast<const float2*>(&g_h2[(size_t)s * HID + lane * 2]);
        a0 += al * v.x; a1 += al * v.y;
    }
    *reinterpret_cast<float2*>(&g_out2[(size_t)d * HID + lane * 2]) = make_float2(a0, a1);
}

// relu(out2 + b2) -> segment (graph) sum + count
__global__ void pool_kernel(const int* __restrict__ batch, const float* __restrict__ b2) {
    int idx = blockIdx.x * 256 + threadIdx.x;
    if (idx >= NN * HID) return;
    int n = idx >> 6, j = idx & 63;
    int g = clampn(batch[n], NGR);
    float v = fmaxf(g_out2[(size_t)n * HID + j] + __ldg(&b2[j]), 0.f);
    atomicAdd(&g_pool[(size_t)g * HID + j], v);
    if (j == 0) atomicAdd(&g_cnt[g], 1.0f);
}

// mean pool -> logits -> log_softmax
__global__ void final_kernel(const float* __restrict__ Wc, const float* __restrict__ bc,
                             float* __restrict__ out) {
    int g = blockIdx.x, j = threadIdx.x;     // 64 threads
    float cnt = g_cnt[g];
    float m = g_pool[(size_t)g * HID + j] / fmaxf(cnt, 1.0f);
    __shared__ float s0[64], s1[64];
    s0[j] = m * Wc[j * 2 + 0];
    s1[j] = m * Wc[j * 2 + 1];
    __syncthreads();
    if (j == 0) {
        float l0 = bc[0], l1 = bc[1];
        for (int i = 0; i < 64; i++) { l0 += s0[i]; l1 += s1[i]; }
        float mx = fmaxf(l0, l1);
        float lse = mx + logf(expf(l0 - mx) + expf(l1 - mx));
        out[g * 2 + 0] = l0 - lse;
        out[g * 2 + 1] = l1 - lse;
    }
}

// ---------------- launch ----------------------------------------------------
extern "C" void kernel_launch(void* const* d_in, const int* in_sizes, int n_in,
                              void* d_out, int out_size) {
    const float* x      = (const float*)d_in[0];
    const int*   ei     = (const int*)d_in[1];     // int32 (JAX x64 disabled)
    const int*   batch  = (const int*)d_in[2];     // int32
    const float* W1     = (const float*)d_in[3];
    const float* a_src1 = (const float*)d_in[4];
    const float* a_dst1 = (const float*)d_in[5];
    const float* b1     = (const float*)d_in[6];
    const float* W2     = (const float*)d_in[7];
    const float* a_src2 = (const float*)d_in[8];
    const float* a_dst2 = (const float*)d_in[9];
    const float* b2     = (const float*)d_in[10];
    const float* Wc     = (const float*)d_in[11];
    const float* bc     = (const float*)d_in[12];
    float* out = (float*)d_out;

    zero_kernel<<<(NN + 255) / 256, 256>>>();
    deg_kernel<<<(ET + 255) / 256, 256>>>(ei);
    scan_kernel<<<1, 1024>>>();
    scatter_kernel<<<(ET + 255) / 256, 256>>>(ei);
    gemm1_kernel<<<dim3((NN + 127) / 128, C1 / 128), 256>>>(x, W1);
    att1_kernel<<<(NN + 7) / 8, 256>>>(a_src1, a_dst1);
    edgeP1_kernel<<<(ET + 255) / 256, 256>>>();
    gather1_kernel<<<(NN + 7) / 8, 256>>>();
    gemm2_kernel<<<(NN + 127) / 128, 256>>>(W2, b1);
    att2_kernel<<<(NN + 7) / 8, 256>>>(a_src2, a_dst2);
    edgeP2_kernel<<<(ET + 255) / 256, 256>>>();
    gather2_kernel<<<(NN + 7) / 8, 256>>>();
    pool_kernel<<<(NN * HID + 255) / 256, 256>>>(batch, b2);
    final_kernel<<<NGR, HID>>>(Wc, bc, out);
}